// round 7
// baseline (speedup 1.0000x reference)
#include <cuda_runtime.h>
#include <math.h>

#define H     4096
#define NB    16
#define BS    256
#define TOPK  4
#define RANK  128
#define MT    128
#define MAXROWS 8192

// ---- device-global scratch (no allocations allowed) ----
__device__ int   g_counts[NB];
__device__ int   g_rows[NB * MAXROWS];
__device__ float g_wts [NB * MAXROWS];

__global__ void zero_counts_kernel() {
    if (threadIdx.x < NB) g_counts[threadIdx.x] = 0;
}

__device__ __forceinline__ float warp_sum(float v) {
    v += __shfl_down_sync(0xffffffffu, v, 16);
    v += __shfl_down_sync(0xffffffffu, v, 8);
    v += __shfl_down_sync(0xffffffffu, v, 4);
    v += __shfl_down_sync(0xffffffffu, v, 2);
    v += __shfl_down_sync(0xffffffffu, v, 1);
    return v;
}

// packed fp32x2 FMA: c.lo += a.lo*b.lo ; c.hi += a.hi*b.hi  (exact IEEE per lane)
__device__ __forceinline__ void ffma2(unsigned long long& c,
                                      unsigned long long a,
                                      unsigned long long b) {
    asm("fma.rn.f32x2 %0, %1, %2, %0;" : "+l"(c) : "l"(a), "l"(b));
}

union F2U { unsigned long long u; float2 f; };

// ---------------------------------------------------------------------------
// Kernel 1: per-row routing + residual copy (out = hidden).
// ---------------------------------------------------------------------------
__global__ void __launch_bounds__(256) route_kernel(
    const float* __restrict__ x, const float* __restrict__ prior,
    const float* __restrict__ sw, const float* __restrict__ sb,
    const float* __restrict__ rps_p, float* __restrict__ out)
{
    const int row = blockIdx.x;
    const float4* xv = (const float4*)(x + (size_t)row * H);
    float4*       ov = (float4*)(out + (size_t)row * H);
    const float4* w0 = (const float4*)(sw);
    const float4* w1 = (const float4*)(sw + H);
    const float4* w2 = (const float4*)(sw + 2 * H);

    float s = 0.f, s2 = 0.f, d0 = 0.f, d1 = 0.f, d2 = 0.f;
    float t0 = 0.f, t1 = 0.f, t2 = 0.f;

    #pragma unroll 4
    for (int i = threadIdx.x; i < H / 4; i += 256) {
        float4 v = xv[i];
        ov[i] = v;                       // fused residual copy
        float4 a = __ldg(&w0[i]);
        float4 b = __ldg(&w1[i]);
        float4 c = __ldg(&w2[i]);
        s  += (v.x + v.y) + (v.z + v.w);
        s2 += v.x * v.x + v.y * v.y + v.z * v.z + v.w * v.w;
        d0 += v.x * a.x + v.y * a.y + v.z * a.z + v.w * a.w;
        d1 += v.x * b.x + v.y * b.y + v.z * b.z + v.w * b.w;
        d2 += v.x * c.x + v.y * c.y + v.z * c.z + v.w * c.w;
        t0 += (a.x + a.y) + (a.z + a.w);
        t1 += (b.x + b.y) + (b.z + b.w);
        t2 += (c.x + c.y) + (c.z + c.w);
    }

    float vals[8] = {s, s2, d0, d1, d2, t0, t1, t2};
    __shared__ float red[8][8];
    const int wid = threadIdx.x >> 5, lane = threadIdx.x & 31;
    #pragma unroll
    for (int j = 0; j < 8; j++) vals[j] = warp_sum(vals[j]);
    if (lane == 0) {
        #pragma unroll
        for (int j = 0; j < 8; j++) red[wid][j] = vals[j];
    }
    __syncthreads();

    if (threadIdx.x == 0) {
        float r[8];
        #pragma unroll
        for (int j = 0; j < 8; j++) {
            float acc = 0.f;
            #pragma unroll
            for (int w = 0; w < 8; w++) acc += red[w][j];
            r[j] = acc;
        }
        const float invH = 1.0f / (float)H;
        float mu  = r[0] * invH;
        float var = fmaxf(r[1] * invH - mu * mu, 0.f);
        float rstd = rsqrtf(var + 1e-5f);
        float q0 = 3.0f / (1.0f + expf(-((r[2] - mu * r[5]) * rstd + sb[0])));
        float q1 = 3.0f / (1.0f + expf(-((r[3] - mu * r[6]) * rstd + sb[1])));
        float q2 = 3.0f / (1.0f + expf(-((r[4] - mu * r[7]) * rstd + sb[2])));

        const float rps = *rps_p;
        const float* pr = prior + (size_t)row * NB;
        float p[NB]; float psum = 0.f;
        #pragma unroll
        for (int i = 0; i < NB; i++) { p[i] = fmaxf(pr[i], 0.f); psum += p[i]; }
        float inv = 1.0f / fmaxf(psum, 1e-6f);

        float fused[NB];
        #pragma unroll
        for (int i = 0; i < NB; i++) {
            float cx = (float)(i & 3);
            float cy = (float)((i >> 2) & 3);
            float dx = q0 - cx, dy = q1 - cy, dz = q2;   // cz == 0 for NB=16
            float sp = expf(-0.5f * (dx * dx + dy * dy + dz * dz));
            float bias = logf(p[i] * inv + 1e-6f);
            bias = fminf(fmaxf(bias, -6.0f), 0.0f);
            fused[i] = sp + rps * bias;
        }
        int   idx[TOPK]; float val[TOPK];
        #pragma unroll
        for (int k = 0; k < TOPK; k++) {
            int bi = 0; float bv = fused[0];
            #pragma unroll
            for (int i = 1; i < NB; i++)
                if (fused[i] > bv) { bv = fused[i]; bi = i; }
            idx[k] = bi; val[k] = bv; fused[bi] = -1e30f;
        }
        float mx = val[0];
        float e[TOPK], es = 0.f;
        #pragma unroll
        for (int k = 0; k < TOPK; k++) { e[k] = expf(val[k] - mx); es += e[k]; }
        float inve = 1.0f / es;
        #pragma unroll
        for (int k = 0; k < TOPK; k++) {
            int pos = atomicAdd(&g_counts[idx[k]], 1);
            if (pos < MAXROWS) {
                g_rows[idx[k] * MAXROWS + pos] = row;
                g_wts [idx[k] * MAXROWS + pos] = e[k] * inve;
            }
        }
    }
}

// ---------------------------------------------------------------------------
// Kernel 2: grouped gather-GEMM adapter, packed f32x2 FMA inner loops.
// smem: Xa 16KB (32-k chunk) + Lo 64KB + 2x8KB duplicated weight stages = 96KB
// -> 2 CTAs/SM. Weight stages ping-pong with register prefetch, one barrier
// per 8-k block. Accumulators packed along m (pairs free from m-contiguous
// Xa / Lo); weight operand staged duplicated {v,v} in smem.
// ---------------------------------------------------------------------------
__global__ void __launch_bounds__(256, 2) adapter_kernel(
    const float* __restrict__ x, const float* __restrict__ down,
    const float* __restrict__ up, const float* __restrict__ rs_p,
    float* __restrict__ out)
{
    const int nb = blockIdx.y;
    const int count = min(g_counts[nb], MAXROWS);
    const int m0 = blockIdx.x * MT;
    if (m0 >= count) return;
    const int M = min(MT, count - m0);

    extern __shared__ float smem[];
    float* Xa  = smem;                 // [32][MT=128] chunk, k-major   (16 KB)
    float* Lo  = Xa + 32 * MT;         // [RANK=128][MT=128]            (64 KB)
    float* Bst = Lo + RANK * MT;       // 2 x 2048 duplicated stages    (16 KB)
    __shared__ int   rows_s[MT];
    __shared__ float wts_s[MT];

    const int tid = threadIdx.x;
    if (tid < MT) {
        if (tid < M) {
            rows_s[tid] = g_rows[nb * MAXROWS + m0 + tid];
            wts_s[tid]  = g_wts [nb * MAXROWS + m0 + tid];
        } else {
            rows_s[tid] = g_rows[nb * MAXROWS + m0];   // valid addr, zero weight
            wts_s[tid]  = 0.f;
        }
    }

    const float* dwn = down + (size_t)nb * (BS * RANK);
    const float* upw = up   + (size_t)nb * (RANK * BS);

    const int ty = tid >> 4, tx = tid & 15;
    const int gm = tid & 127, seg = tid >> 7;     // gather: row gm, k-seg
    const int sk = tid >> 5, sc = tid & 31;       // stage:  k-row sk, col sc

    // prefetch first down-weight stage (8 k x 128 d)
    float4 w = ((const float4*)dwn)[tid];

    unsigned long long accp[8][4];
    #pragma unroll
    for (int i = 0; i < 8; i++)
        #pragma unroll
        for (int j = 0; j < 4; j++) accp[i][j] = 0ull;

    int p = 0;

    // ---- GEMM1: Lo[d][m] = sum_k down[k][d] * Xa[k][m], 8 chunks of 32 k ----
    for (int kc = 0; kc < 8; kc++) {
        __syncthreads();   // prev chunk compute done (and rows_s visible at kc=0)
        {   // gather chunk: 32 k x 128 m ; thread -> (row gm, k in [seg*16,+16))
            const float4* src = (const float4*)(x + (size_t)rows_s[gm] * H
                                                + nb * BS + kc * 32 + seg * 16);
            float4 g0 = src[0], g1 = src[1], g2 = src[2], g3 = src[3];
            int kb = seg * 16;
            Xa[(kb+ 0)*MT+gm]=g0.x; Xa[(kb+ 1)*MT+gm]=g0.y; Xa[(kb+ 2)*MT+gm]=g0.z; Xa[(kb+ 3)*MT+gm]=g0.w;
            Xa[(kb+ 4)*MT+gm]=g1.x; Xa[(kb+ 5)*MT+gm]=g1.y; Xa[(kb+ 6)*MT+gm]=g1.z; Xa[(kb+ 7)*MT+gm]=g1.w;
            Xa[(kb+ 8)*MT+gm]=g2.x; Xa[(kb+ 9)*MT+gm]=g2.y; Xa[(kb+10)*MT+gm]=g2.z; Xa[(kb+11)*MT+gm]=g2.w;
            Xa[(kb+12)*MT+gm]=g3.x; Xa[(kb+13)*MT+gm]=g3.y; Xa[(kb+14)*MT+gm]=g3.z; Xa[(kb+15)*MT+gm]=g3.w;
        }
        for (int b8 = 0; b8 < 4; b8++) {
            {   // store duplicated stage: value d at positions k*256 + 2d, 2d+1
                float4* dst = (float4*)(Bst + p * 2048) + 2 * tid;
                dst[0] = make_float4(w.x, w.x, w.y, w.y);
                dst[1] = make_float4(w.z, w.z, w.w, w.w);
            }
            __syncthreads();
            int nxt = kc * 4 + b8 + 1;
            if (nxt < 32) {
                w = ((const float4*)(dwn + nxt * 8 * RANK))[tid];
            } else {
                // prefetch first up-weight stage for GEMM2 (h=0, kb=0)
                w = ((const float4*)(upw + sk * BS))[sc];
            }
            const float* Bp = Bst + p * 2048;
            #pragma unroll
            for (int k = 0; k < 8; k++) {
                unsigned long long ad[8], bp[4];
                const float* arow = Bp + k * 256 + 2 * (ty * 8);
                #pragma unroll
                for (int i = 0; i < 8; i++)
                    ad[i] = *(const unsigned long long*)(arow + 2 * i);
                const float* Xp = &Xa[(b8 * 8 + k) * MT + tx * 8];
                ulonglong2 q0 = *(const ulonglong2*)Xp;
                ulonglong2 q1 = *(const ulonglong2*)(Xp + 4);
                bp[0] = q0.x; bp[1] = q0.y; bp[2] = q1.x; bp[3] = q1.y;
                #pragma unroll
                for (int i = 0; i < 8; i++)
                    #pragma unroll
                    for (int j = 0; j < 4; j++)
                        ffma2(accp[i][j], ad[i], bp[j]);
            }
            p ^= 1;
        }
    }

    // write Lo (pairs are m-contiguous), then barrier for GEMM2 reads
    #pragma unroll
    for (int i = 0; i < 8; i++) {
        int d = ty * 8 + i;
        #pragma unroll
        for (int j = 0; j < 4; j++)
            *(unsigned long long*)&Lo[d * MT + tx * 8 + 2 * j] = accp[i][j];
    }
    __syncthreads();

    // ---- GEMM2: out[m][n] += rs*w_m * sum_d Lo[d][m]*up[d][n], halves of 128 n
    // stage layout: value (k, n) duplicated at k*256 + 2*((n&7)*16 + (n>>3))
    const float rs = *rs_p;
    for (int h = 0; h < 2; h++) {
        unsigned long long acc2p[4][8];
        #pragma unroll
        for (int i = 0; i < 4; i++)
            #pragma unroll
            for (int j = 0; j < 8; j++) acc2p[i][j] = 0ull;

        for (int b8 = 0; b8 < 16; b8++) {
            {   // store duplicated+permuted stage; w covers n = 4*sc + q, k = sk
                float* base = Bst + p * 2048 + sk * 256;
                const float* wv = &w.x;
                #pragma unroll
                for (int q = 0; q < 4; q++) {
                    int n = 4 * sc + q;
                    float v = wv[q];
                    *(float2*)(base + 2 * (((n & 7) << 4) + (n >> 3))) = make_float2(v, v);
                }
            }
            __syncthreads();
            int t = h * 16 + b8 + 1;
            if (t < 32) {
                w = ((const float4*)(upw + ((t & 15) * 8 + sk) * BS
                                     + (t >> 4) * 128))[sc];
            }
            const float* Bp = Bst + p * 2048;
            #pragma unroll
            for (int k = 0; k < 8; k++) {
                unsigned long long ap[4], bd[8];
                const float* Lp = &Lo[(b8 * 8 + k) * MT + ty * 8];
                #pragma unroll
                for (int i = 0; i < 4; i++)
                    ap[i] = *(const unsigned long long*)(Lp + 2 * i);
                const float* brow = Bp + k * 256 + 2 * tx;   // perm: +32 per j
                #pragma unroll
                for (int j = 0; j < 8; j++)
                    bd[j] = *(const unsigned long long*)(brow + 32 * j);
                #pragma unroll
                for (int i = 0; i < 4; i++)
                    #pragma unroll
                    for (int j = 0; j < 8; j++)
                        ffma2(acc2p[i][j], ap[i], bd[j]);
            }
            p ^= 1;
        }
        // epilogue: out += rs * w_m * acc2   (out already holds hidden)
        #pragma unroll
        for (int i = 0; i < 8; i++) {
            int m = ty * 8 + i;
            if (m < M) {
                float scale = rs * wts_s[m];
                float v[8];
                #pragma unroll
                for (int j = 0; j < 8; j++) {
                    F2U u; u.u = acc2p[i >> 1][j];
                    v[j] = (i & 1) ? u.f.y : u.f.x;
                }
                float* o = out + (size_t)rows_s[m] * H + nb * BS + h * 128 + tx * 8;
                float4 v0 = *(float4*)o;
                v0.x += scale * v[0]; v0.y += scale * v[1];
                v0.z += scale * v[2]; v0.w += scale * v[3];
                *(float4*)o = v0;
                float4 v1 = *(float4*)(o + 4);
                v1.x += scale * v[4]; v1.y += scale * v[5];
                v1.z += scale * v[6]; v1.w += scale * v[7];
                *(float4*)(o + 4) = v1;
            }
        }
    }
}

// ---------------------------------------------------------------------------
extern "C" void kernel_launch(void* const* d_in, const int* in_sizes, int n_in,
                              void* d_out, int out_size)
{
    const float* x     = (const float*)d_in[0];
    const float* prior = (const float*)d_in[1];
    const float* sw    = (const float*)d_in[2];
    const float* sb    = (const float*)d_in[3];
    const float* dw    = (const float*)d_in[4];
    const float* uw    = (const float*)d_in[5];
    const float* rps   = (const float*)d_in[6];
    const float* rs    = (const float*)d_in[7];
    float* out = (float*)d_out;

    int rows = in_sizes[0] / H;   // 8192
    if (rows > MAXROWS) rows = MAXROWS;

    int smem_bytes = (32 * MT + RANK * MT + 2 * 2048) * (int)sizeof(float);  // 98304
    cudaFuncSetAttribute(adapter_kernel,
                         cudaFuncAttributeMaxDynamicSharedMemorySize, smem_bytes);

    zero_counts_kernel<<<1, 32>>>();
    route_kernel<<<rows, 256>>>(x, prior, sw, sb, rps, out);
    dim3 g2((rows + MT - 1) / MT, NB);
    adapter_kernel<<<g2, 256, smem_bytes>>>(x, dw, uw, rs, out);
}

// round 10
// speedup vs baseline: 1.2584x; 1.2584x over previous
#include <cuda_runtime.h>
#include <cuda_bf16.h>
#include <math.h>
#include <stdint.h>

#define H     4096
#define NB    16
#define BS    256
#define TOPK  4
#define RANK  128
#define MT    128
#define MAXROWS 8192

// ---- device-global scratch (no allocations allowed) ----
__device__ int   g_counts[NB];
__device__ int   g_rows[NB * MAXROWS];
__device__ float g_wts [NB * MAXROWS];
// bf16 weights, pre-transposed to mma row.col B layout (k-contiguous):
// g_Bd[nb]: down^T  [128 d][256 k]   g_Bu[nb]: up^T [256 n][128 d]
__device__ uint4 g_Bd[NB * 4096];
__device__ uint4 g_Bu[NB * 4096];

__global__ void zero_counts_kernel() {
    if (threadIdx.x < NB) g_counts[threadIdx.x] = 0;
}

__device__ __forceinline__ uint32_t smem_u32(const void* p) {
    uint32_t a;
    asm("{ .reg .u64 t; cvta.to.shared.u64 t, %1; cvt.u32.u64 %0, t; }"
        : "=r"(a) : "l"(p));
    return a;
}

__device__ __forceinline__ uint32_t pack_bf2(float a, float b) {
    uint16_t ua = __bfloat16_as_ushort(__float2bfloat16_rn(a));
    uint16_t ub = __bfloat16_as_ushort(__float2bfloat16_rn(b));
    return (uint32_t)ua | ((uint32_t)ub << 16);
}

__device__ __forceinline__ void ldmx4(uint32_t* r, uint32_t addr) {
    asm volatile("ldmatrix.sync.aligned.m8n8.x4.shared.b16 {%0,%1,%2,%3}, [%4];"
                 : "=r"(r[0]), "=r"(r[1]), "=r"(r[2]), "=r"(r[3]) : "r"(addr));
}
__device__ __forceinline__ void ldmx2(uint32_t* r, uint32_t addr) {
    asm volatile("ldmatrix.sync.aligned.m8n8.x2.shared.b16 {%0,%1}, [%2];"
                 : "=r"(r[0]), "=r"(r[1]) : "r"(addr));
}
__device__ __forceinline__ void mma_bf16(float* c, const uint32_t* a, const uint32_t* b) {
    asm volatile(
        "mma.sync.aligned.m16n8k16.row.col.f32.bf16.bf16.f32 "
        "{%0,%1,%2,%3}, {%4,%5,%6,%7}, {%8,%9}, {%0,%1,%2,%3};"
        : "+f"(c[0]), "+f"(c[1]), "+f"(c[2]), "+f"(c[3])
        : "r"(a[0]), "r"(a[1]), "r"(a[2]), "r"(a[3]), "r"(b[0]), "r"(b[1]));
}

__device__ __forceinline__ float warp_sum(float v) {
    v += __shfl_down_sync(0xffffffffu, v, 16);
    v += __shfl_down_sync(0xffffffffu, v, 8);
    v += __shfl_down_sync(0xffffffffu, v, 4);
    v += __shfl_down_sync(0xffffffffu, v, 2);
    v += __shfl_down_sync(0xffffffffu, v, 1);
    return v;
}

// ---------------------------------------------------------------------------
// Weight pre-conversion (transpose + bf16), once per launch.
// ---------------------------------------------------------------------------
__global__ void __launch_bounds__(256) convert_weights_kernel(
    const float* __restrict__ down, const float* __restrict__ up)
{
    const int nb = blockIdx.x;
    if (blockIdx.y == 0) {
        const float* src = down + (size_t)nb * BS * RANK;     // [k][d]
        __nv_bfloat16* dst = (__nv_bfloat16*)g_Bd + (size_t)nb * 32768;
        for (int i = threadIdx.x; i < BS * RANK; i += 256) {
            int k = i >> 7, d = i & 127;
            dst[d * 256 + k] = __float2bfloat16_rn(src[i]);
        }
    } else {
        const float* src = up + (size_t)nb * RANK * BS;       // [d][n]
        __nv_bfloat16* dst = (__nv_bfloat16*)g_Bu + (size_t)nb * 32768;
        for (int i = threadIdx.x; i < RANK * BS; i += 256) {
            int d = i >> 8, n = i & 255;
            dst[n * 128 + d] = __float2bfloat16_rn(src[i]);
        }
    }
}

// ---------------------------------------------------------------------------
// Kernel 1: per-row routing + residual copy (out = hidden). (unchanged)
// ---------------------------------------------------------------------------
__global__ void __launch_bounds__(256) route_kernel(
    const float* __restrict__ x, const float* __restrict__ prior,
    const float* __restrict__ sw, const float* __restrict__ sb,
    const float* __restrict__ rps_p, float* __restrict__ out)
{
    const int row = blockIdx.x;
    const float4* xv = (const float4*)(x + (size_t)row * H);
    float4*       ov = (float4*)(out + (size_t)row * H);
    const float4* w0 = (const float4*)(sw);
    const float4* w1 = (const float4*)(sw + H);
    const float4* w2 = (const float4*)(sw + 2 * H);

    float s = 0.f, s2 = 0.f, d0 = 0.f, d1 = 0.f, d2 = 0.f;
    float t0 = 0.f, t1 = 0.f, t2 = 0.f;

    #pragma unroll 4
    for (int i = threadIdx.x; i < H / 4; i += 256) {
        float4 v = xv[i];
        ov[i] = v;
        float4 a = __ldg(&w0[i]);
        float4 b = __ldg(&w1[i]);
        float4 c = __ldg(&w2[i]);
        s  += (v.x + v.y) + (v.z + v.w);
        s2 += v.x * v.x + v.y * v.y + v.z * v.z + v.w * v.w;
        d0 += v.x * a.x + v.y * a.y + v.z * a.z + v.w * a.w;
        d1 += v.x * b.x + v.y * b.y + v.z * b.z + v.w * b.w;
        d2 += v.x * c.x + v.y * c.y + v.z * c.z + v.w * c.w;
        t0 += (a.x + a.y) + (a.z + a.w);
        t1 += (b.x + b.y) + (b.z + b.w);
        t2 += (c.x + c.y) + (c.z + c.w);
    }

    float vals[8] = {s, s2, d0, d1, d2, t0, t1, t2};
    __shared__ float red[8][8];
    const int wid = threadIdx.x >> 5, lane = threadIdx.x & 31;
    #pragma unroll
    for (int j = 0; j < 8; j++) vals[j] = warp_sum(vals[j]);
    if (lane == 0) {
        #pragma unroll
        for (int j = 0; j < 8; j++) red[wid][j] = vals[j];
    }
    __syncthreads();

    if (threadIdx.x == 0) {
        float r[8];
        #pragma unroll
        for (int j = 0; j < 8; j++) {
            float acc = 0.f;
            #pragma unroll
            for (int w = 0; w < 8; w++) acc += red[w][j];
            r[j] = acc;
        }
        const float invH = 1.0f / (float)H;
        float mu  = r[0] * invH;
        float var = fmaxf(r[1] * invH - mu * mu, 0.f);
        float rstd = rsqrtf(var + 1e-5f);
        float q0 = 3.0f / (1.0f + expf(-((r[2] - mu * r[5]) * rstd + sb[0])));
        float q1 = 3.0f / (1.0f + expf(-((r[3] - mu * r[6]) * rstd + sb[1])));
        float q2 = 3.0f / (1.0f + expf(-((r[4] - mu * r[7]) * rstd + sb[2])));

        const float rps = *rps_p;
        const float* pr = prior + (size_t)row * NB;
        float p[NB]; float psum = 0.f;
        #pragma unroll
        for (int i = 0; i < NB; i++) { p[i] = fmaxf(pr[i], 0.f); psum += p[i]; }
        float inv = 1.0f / fmaxf(psum, 1e-6f);

        float fused[NB];
        #pragma unroll
        for (int i = 0; i < NB; i++) {
            float cx = (float)(i & 3);
            float cy = (float)((i >> 2) & 3);
            float dx = q0 - cx, dy = q1 - cy, dz = q2;
            float sp = expf(-0.5f * (dx * dx + dy * dy + dz * dz));
            float bias = logf(p[i] * inv + 1e-6f);
            bias = fminf(fmaxf(bias, -6.0f), 0.0f);
            fused[i] = sp + rps * bias;
        }
        int   idx[TOPK]; float val[TOPK];
        #pragma unroll
        for (int k = 0; k < TOPK; k++) {
            int bi = 0; float bv = fused[0];
            #pragma unroll
            for (int i = 1; i < NB; i++)
                if (fused[i] > bv) { bv = fused[i]; bi = i; }
            idx[k] = bi; val[k] = bv; fused[bi] = -1e30f;
        }
        float mx = val[0];
        float e[TOPK], es = 0.f;
        #pragma unroll
        for (int k = 0; k < TOPK; k++) { e[k] = expf(val[k] - mx); es += e[k]; }
        float inve = 1.0f / es;
        #pragma unroll
        for (int k = 0; k < TOPK; k++) {
            int pos = atomicAdd(&g_counts[idx[k]], 1);
            if (pos < MAXROWS) {
                g_rows[idx[k] * MAXROWS + pos] = row;
                g_wts [idx[k] * MAXROWS + pos] = e[k] * inve;
            }
        }
    }
}

// ---------------------------------------------------------------------------
// Kernel 2: warp-MMA adapter (bf16 HMMA, fp32 accum).
// smem rows padded to 272B (68 u32, 68 % 32 == 4 -> ldmatrix conflict-free).
// Region A (34816B): X chunk [128][136bf16] / Lo ; Region B (69632B):
// down chunk [128][136] / up full [256][136].
// ---------------------------------------------------------------------------
__global__ void __launch_bounds__(256) adapter_kernel(
    const float* __restrict__ x, const float* __restrict__ rs_p,
    float* __restrict__ out)
{
    const int nb = blockIdx.y;
    const int count = min(g_counts[nb], MAXROWS);
    const int m0 = blockIdx.x * MT;
    if (m0 >= count) return;
    const int M = min(MT, count - m0);

    extern __shared__ uint4 s4[];
    uint32_t* s32 = (uint32_t*)s4;
    const uint32_t sbase = smem_u32(s4);
    __shared__ int   rows_s[MT];
    __shared__ float wts_s[MT];

    const int tid  = threadIdx.x;
    const int lane = tid & 31, w = tid >> 5;
    const int m_base = (w >> 2) * 64, n_base = (w & 3) * 32;

    if (tid < MT) {
        if (tid < M) {
            rows_s[tid] = g_rows[nb * MAXROWS + m0 + tid];
            wts_s[tid]  = g_wts [nb * MAXROWS + m0 + tid];
        } else {
            rows_s[tid] = g_rows[nb * MAXROWS + m0];
            wts_s[tid]  = 0.f;
        }
    }

    float c[4][4][4];

    // =================== GEMM1: C1[128m][128d] = X @ down^T ===================
    #pragma unroll
    for (int mi = 0; mi < 4; mi++)
        #pragma unroll
        for (int ni = 0; ni < 4; ni++)
            #pragma unroll
            for (int q = 0; q < 4; q++) c[mi][ni][q] = 0.f;

    for (int kc = 0; kc < 2; kc++) {
        __syncthreads();
        {   // stage X chunk (fp32 -> bf16): row = tid/2, 64 k per half-thread
            const int row = tid >> 1, half = tid & 1;
            const float4* src = (const float4*)(x + (size_t)rows_s[row] * H
                                                + nb * BS + kc * 128 + half * 64);
            uint4* dst = s4 + row * 17 + half * 8;
            #pragma unroll
            for (int j = 0; j < 8; j++) {
                float4 u = src[2 * j], v = src[2 * j + 1];
                uint4 t;
                t.x = pack_bf2(u.x, u.y); t.y = pack_bf2(u.z, u.w);
                t.z = pack_bf2(v.x, v.y); t.w = pack_bf2(v.z, v.w);
                dst[j] = t;
            }
        }
        {   // stage down chunk [128 d][128 k]
            const int row = tid >> 1, half = tid & 1;
            const uint4* src = g_Bd + nb * 4096 + row * 32 + kc * 16 + half * 8;
            uint4* dst = s4 + 2176 + row * 17 + half * 8;
            #pragma unroll
            for (int j = 0; j < 8; j++) dst[j] = src[j];
        }
        __syncthreads();

        const uint32_t xb = sbase;
        const uint32_t db = sbase + 34816;
        #pragma unroll
        for (int ks = 0; ks < 8; ks++) {
            uint32_t a[4][4], b[4][2];
            int acol = ks * 16 + 8 * (lane >> 4);
            #pragma unroll
            for (int mi = 0; mi < 4; mi++)
                ldmx4(a[mi], xb + (m_base + mi * 16 + (lane & 15)) * 272 + acol * 2);
            int bcol = ks * 16 + 8 * ((lane >> 3) & 1);
            #pragma unroll
            for (int ni = 0; ni < 4; ni++)
                ldmx2(b[ni], db + (n_base + ni * 8 + (lane & 7)) * 272 + bcol * 2);
            #pragma unroll
            for (int mi = 0; mi < 4; mi++)
                #pragma unroll
                for (int ni = 0; ni < 4; ni++)
                    mma_bf16(c[mi][ni], a[mi], b[ni]);
        }
    }
    __syncthreads();   // all reads of X/down done before overwrite

    // write Lo = bf16(C1) into region A; copy up^T full into region B
    #pragma unroll
    for (int mi = 0; mi < 4; mi++)
        #pragma unroll
        for (int ni = 0; ni < 4; ni++) {
            int r0 = m_base + mi * 16 + (lane >> 2);
            int cp = ((n_base + ni * 8) >> 1) + (lane & 3);
            s32[r0 * 68 + cp]       = pack_bf2(c[mi][ni][0], c[mi][ni][1]);
            s32[(r0 + 8) * 68 + cp] = pack_bf2(c[mi][ni][2], c[mi][ni][3]);
        }
    {
        const uint4* src = g_Bu + nb * 4096 + tid * 16;
        uint4* dst = s4 + 2176 + tid * 17;
        #pragma unroll
        for (int j = 0; j < 16; j++) dst[j] = src[j];
    }
    __syncthreads();

    // =================== GEMM2: out += rs*w_m * (Lo @ up^T) ===================
    const float rs = *rs_p;
    for (int half = 0; half < 2; half++) {
        #pragma unroll
        for (int mi = 0; mi < 4; mi++)
            #pragma unroll
            for (int ni = 0; ni < 4; ni++)
                #pragma unroll
                for (int q = 0; q < 4; q++) c[mi][ni][q] = 0.f;

        const uint32_t lb = sbase;
        const uint32_t ub = sbase + 34816;
        #pragma unroll
        for (int ks = 0; ks < 8; ks++) {
            uint32_t a[4][4], b[4][2];
            int acol = ks * 16 + 8 * (lane >> 4);
            #pragma unroll
            for (int mi = 0; mi < 4; mi++)
                ldmx4(a[mi], lb + (m_base + mi * 16 + (lane & 15)) * 272 + acol * 2);
            int bcol = ks * 16 + 8 * ((lane >> 3) & 1);
            #pragma unroll
            for (int ni = 0; ni < 4; ni++)
                ldmx2(b[ni], ub + (half * 128 + n_base + ni * 8 + (lane & 7)) * 272 + bcol * 2);
            #pragma unroll
            for (int mi = 0; mi < 4; mi++)
                #pragma unroll
                for (int ni = 0; ni < 4; ni++)
                    mma_bf16(c[mi][ni], a[mi], b[ni]);
        }
        // epilogue: RMW out
        #pragma unroll
        for (int mi = 0; mi < 4; mi++) {
            #pragma unroll
            for (int rsel = 0; rsel < 2; rsel++) {
                int m = m_base + mi * 16 + (lane >> 2) + rsel * 8;
                if (m < M) {
                    float sc = rs * wts_s[m];
                    float* o = out + (size_t)rows_s[m] * H + nb * BS
                             + half * 128 + n_base + (lane & 3) * 2;
                    #pragma unroll
                    for (int ni = 0; ni < 4; ni++) {
                        float2* p = (float2*)(o + ni * 8);
                        float2 t = *p;
                        t.x += sc * c[mi][ni][rsel * 2];
                        t.y += sc * c[mi][ni][rsel * 2 + 1];
                        *p = t;
                    }
                }
            }
        }
    }
}

// ---------------------------------------------------------------------------
extern "C" void kernel_launch(void* const* d_in, const int* in_sizes, int n_in,
                              void* d_out, int out_size)
{
    const float* x     = (const float*)d_in[0];
    const float* prior = (const float*)d_in[1];
    const float* sw    = (const float*)d_in[2];
    const float* sb    = (const float*)d_in[3];
    const float* dw    = (const float*)d_in[4];
    const float* uw    = (const float*)d_in[5];
    const float* rps   = (const float*)d_in[6];
    const float* rs    = (const float*)d_in[7];
    float* out = (float*)d_out;

    int rows = in_sizes[0] / H;   // 8192
    if (rows > MAXROWS) rows = MAXROWS;

    int smem_bytes = 34816 + 69632;   // 104448
    cudaFuncSetAttribute(adapter_kernel,
                         cudaFuncAttributeMaxDynamicSharedMemorySize, smem_bytes);

    zero_counts_kernel<<<1, 32>>>();
    convert_weights_kernel<<<dim3(NB, 2), 256>>>(dw, uw);
    route_kernel<<<rows, 256>>>(x, prior, sw, sb, rps, out);
    dim3 g2((rows + MT - 1) / MT, NB);
    adapter_kernel<<<g2, 256, smem_bytes>>>(x, rs, out);
}

// round 11
// speedup vs baseline: 1.3466x; 1.0701x over previous
#include <cuda_runtime.h>
#include <cuda_bf16.h>
#include <math.h>
#include <stdint.h>

#define H     4096
#define NB    16
#define BS    256
#define TOPK  4
#define RANK  128
#define MT    128
#define MAXROWS 8192
#define RPC   8        // rows per route CTA

// ---- device-global scratch (no allocations allowed) ----
__device__ int   g_counts[NB];
__device__ int   g_rows[NB * MAXROWS];
__device__ float g_wts [NB * MAXROWS];
// bf16 weights, pre-transposed to mma row.col B layout (k-contiguous):
// g_Bd[nb]: down^T  [128 d][256 k]   g_Bu[nb]: up^T [256 n][128 d]
__device__ uint4 g_Bd[NB * 4096];
__device__ uint4 g_Bu[NB * 4096];

__global__ void zero_counts_kernel() {
    if (threadIdx.x < NB) g_counts[threadIdx.x] = 0;
}

__device__ __forceinline__ uint32_t smem_u32(const void* p) {
    uint32_t a;
    asm("{ .reg .u64 t; cvta.to.shared.u64 t, %1; cvt.u32.u64 %0, t; }"
        : "=r"(a) : "l"(p));
    return a;
}

__device__ __forceinline__ uint32_t pack_bf2(float a, float b) {
    uint16_t ua = __bfloat16_as_ushort(__float2bfloat16_rn(a));
    uint16_t ub = __bfloat16_as_ushort(__float2bfloat16_rn(b));
    return (uint32_t)ua | ((uint32_t)ub << 16);
}

__device__ __forceinline__ void ldmx4(uint32_t* r, uint32_t addr) {
    asm volatile("ldmatrix.sync.aligned.m8n8.x4.shared.b16 {%0,%1,%2,%3}, [%4];"
                 : "=r"(r[0]), "=r"(r[1]), "=r"(r[2]), "=r"(r[3]) : "r"(addr));
}
__device__ __forceinline__ void ldmx2(uint32_t* r, uint32_t addr) {
    asm volatile("ldmatrix.sync.aligned.m8n8.x2.shared.b16 {%0,%1}, [%2];"
                 : "=r"(r[0]), "=r"(r[1]) : "r"(addr));
}
__device__ __forceinline__ void mma_bf16(float* c, const uint32_t* a, const uint32_t* b) {
    asm volatile(
        "mma.sync.aligned.m16n8k16.row.col.f32.bf16.bf16.f32 "
        "{%0,%1,%2,%3}, {%4,%5,%6,%7}, {%8,%9}, {%0,%1,%2,%3};"
        : "+f"(c[0]), "+f"(c[1]), "+f"(c[2]), "+f"(c[3])
        : "r"(a[0]), "r"(a[1]), "r"(a[2]), "r"(a[3]), "r"(b[0]), "r"(b[1]));
}

__device__ __forceinline__ float warp_sum(float v) {
    v += __shfl_down_sync(0xffffffffu, v, 16);
    v += __shfl_down_sync(0xffffffffu, v, 8);
    v += __shfl_down_sync(0xffffffffu, v, 4);
    v += __shfl_down_sync(0xffffffffu, v, 2);
    v += __shfl_down_sync(0xffffffffu, v, 1);
    return v;
}

// ---------------------------------------------------------------------------
// Weight pre-conversion (transpose + bf16), once per launch.
// ---------------------------------------------------------------------------
__global__ void __launch_bounds__(256) convert_weights_kernel(
    const float* __restrict__ down, const float* __restrict__ up)
{
    const int nb = blockIdx.x;
    if (blockIdx.y == 0) {
        const float* src = down + (size_t)nb * BS * RANK;     // [k][d]
        __nv_bfloat16* dst = (__nv_bfloat16*)g_Bd + (size_t)nb * 32768;
        for (int i = threadIdx.x; i < BS * RANK; i += 256) {
            int k = i >> 7, d = i & 127;
            dst[d * 256 + k] = __float2bfloat16_rn(src[i]);
        }
    } else {
        const float* src = up + (size_t)nb * RANK * BS;       // [d][n]
        __nv_bfloat16* dst = (__nv_bfloat16*)g_Bu + (size_t)nb * 32768;
        for (int i = threadIdx.x; i < RANK * BS; i += 256) {
            int d = i >> 8, n = i & 255;
            dst[n * 128 + d] = __float2bfloat16_rn(src[i]);
        }
    }
}

// ---------------------------------------------------------------------------
// Kernel 1: routing + residual copy. 8 rows per CTA, one warp per row,
// spatial weights staged once in smem (kills 400 MB of L2 weight re-reads).
// ---------------------------------------------------------------------------
__global__ void __launch_bounds__(256) route_kernel(
    const float* __restrict__ x, const float* __restrict__ prior,
    const float* __restrict__ sw, const float* __restrict__ sb,
    const float* __restrict__ rps_p, float* __restrict__ out, int rows)
{
    __shared__ float4 swv[3 * 1024];   // 48 KB: w0|w1|w2 as float4

    const int tid = threadIdx.x;
    for (int i = tid; i < 3 * 1024; i += 256) swv[i] = ((const float4*)sw)[i];
    __syncthreads();

    const int wid = tid >> 5, lane = tid & 31;
    const int row = blockIdx.x * RPC + wid;
    if (row >= rows) return;

    const float4* xv = (const float4*)(x + (size_t)row * H);
    float4*       ov = (float4*)(out + (size_t)row * H);

    float s = 0.f, s2 = 0.f, d0 = 0.f, d1 = 0.f, d2 = 0.f;
    float t0 = 0.f, t1 = 0.f, t2 = 0.f;

    #pragma unroll 4
    for (int i = lane; i < 1024; i += 32) {
        float4 v = xv[i];
        ov[i] = v;                       // fused residual copy
        float4 a = swv[i];
        float4 b = swv[i + 1024];
        float4 c = swv[i + 2048];
        s  += (v.x + v.y) + (v.z + v.w);
        s2 += v.x * v.x + v.y * v.y + v.z * v.z + v.w * v.w;
        d0 += v.x * a.x + v.y * a.y + v.z * a.z + v.w * a.w;
        d1 += v.x * b.x + v.y * b.y + v.z * b.z + v.w * b.w;
        d2 += v.x * c.x + v.y * c.y + v.z * c.z + v.w * c.w;
        t0 += (a.x + a.y) + (a.z + a.w);
        t1 += (b.x + b.y) + (b.z + b.w);
        t2 += (c.x + c.y) + (c.z + c.w);
    }

    float r[8] = {s, s2, d0, d1, d2, t0, t1, t2};
    #pragma unroll
    for (int j = 0; j < 8; j++) r[j] = warp_sum(r[j]);

    if (lane == 0) {
        const float invH = 1.0f / (float)H;
        float mu  = r[0] * invH;
        float var = fmaxf(r[1] * invH - mu * mu, 0.f);
        float rstd = rsqrtf(var + 1e-5f);
        float q0 = 3.0f / (1.0f + expf(-((r[2] - mu * r[5]) * rstd + sb[0])));
        float q1 = 3.0f / (1.0f + expf(-((r[3] - mu * r[6]) * rstd + sb[1])));
        float q2 = 3.0f / (1.0f + expf(-((r[4] - mu * r[7]) * rstd + sb[2])));

        const float rps = *rps_p;
        const float* pr = prior + (size_t)row * NB;
        float p[NB]; float psum = 0.f;
        #pragma unroll
        for (int i = 0; i < NB; i++) { p[i] = fmaxf(pr[i], 0.f); psum += p[i]; }
        float inv = 1.0f / fmaxf(psum, 1e-6f);

        float fused[NB];
        #pragma unroll
        for (int i = 0; i < NB; i++) {
            float cx = (float)(i & 3);
            float cy = (float)((i >> 2) & 3);
            float dx = q0 - cx, dy = q1 - cy, dz = q2;
            float sp = expf(-0.5f * (dx * dx + dy * dy + dz * dz));
            float bias = logf(p[i] * inv + 1e-6f);
            bias = fminf(fmaxf(bias, -6.0f), 0.0f);
            fused[i] = sp + rps * bias;
        }
        int   idx[TOPK]; float val[TOPK];
        #pragma unroll
        for (int k = 0; k < TOPK; k++) {
            int bi = 0; float bv = fused[0];
            #pragma unroll
            for (int i = 1; i < NB; i++)
                if (fused[i] > bv) { bv = fused[i]; bi = i; }
            idx[k] = bi; val[k] = bv; fused[bi] = -1e30f;
        }
        float mx = val[0];
        float e[TOPK], es = 0.f;
        #pragma unroll
        for (int k = 0; k < TOPK; k++) { e[k] = expf(val[k] - mx); es += e[k]; }
        float inve = 1.0f / es;
        #pragma unroll
        for (int k = 0; k < TOPK; k++) {
            int pos = atomicAdd(&g_counts[idx[k]], 1);
            if (pos < MAXROWS) {
                g_rows[idx[k] * MAXROWS + pos] = row;
                g_wts [idx[k] * MAXROWS + pos] = e[k] * inve;
            }
        }
    }
}

// ---------------------------------------------------------------------------
// Kernel 2: warp-MMA adapter (bf16 HMMA, fp32 accum). 2 CTAs/SM forced.
// smem rows padded to 272B (68 u32, 68 % 32 == 4 -> ldmatrix conflict-free).
// Region A (34816B): X chunk [128][136bf16] / Lo ; Region B (69632B):
// down chunk [128][136] / up full [256][136].
// ---------------------------------------------------------------------------
__global__ void __launch_bounds__(256, 2) adapter_kernel(
    const float* __restrict__ x, const float* __restrict__ rs_p,
    float* __restrict__ out)
{
    const int nb = blockIdx.y;
    const int count = min(g_counts[nb], MAXROWS);
    const int m0 = blockIdx.x * MT;
    if (m0 >= count) return;
    const int M = min(MT, count - m0);

    extern __shared__ uint4 s4[];
    uint32_t* s32 = (uint32_t*)s4;
    const uint32_t sbase = smem_u32(s4);
    __shared__ int   rows_s[MT];
    __shared__ float wts_s[MT];

    const int tid  = threadIdx.x;
    const int lane = tid & 31, w = tid >> 5;
    const int m_base = (w >> 2) * 64, n_base = (w & 3) * 32;

    if (tid < MT) {
        if (tid < M) {
            rows_s[tid] = g_rows[nb * MAXROWS + m0 + tid];
            wts_s[tid]  = g_wts [nb * MAXROWS + m0 + tid];
        } else {
            rows_s[tid] = g_rows[nb * MAXROWS + m0];
            wts_s[tid]  = 0.f;
        }
    }

    float c[4][4][4];

    // =================== GEMM1: C1[128m][128d] = X @ down^T ===================
    #pragma unroll
    for (int mi = 0; mi < 4; mi++)
        #pragma unroll
        for (int ni = 0; ni < 4; ni++)
            #pragma unroll
            for (int q = 0; q < 4; q++) c[mi][ni][q] = 0.f;

    for (int kc = 0; kc < 2; kc++) {
        __syncthreads();
        {   // stage X chunk (fp32 -> bf16): row = tid/2, 64 k per half-thread
            const int row = tid >> 1, half = tid & 1;
            const float4* src = (const float4*)(x + (size_t)rows_s[row] * H
                                                + nb * BS + kc * 128 + half * 64);
            uint4* dst = s4 + row * 17 + half * 8;
            #pragma unroll
            for (int j = 0; j < 8; j++) {
                float4 u = src[2 * j], v = src[2 * j + 1];
                uint4 t;
                t.x = pack_bf2(u.x, u.y); t.y = pack_bf2(u.z, u.w);
                t.z = pack_bf2(v.x, v.y); t.w = pack_bf2(v.z, v.w);
                dst[j] = t;
            }
        }
        {   // stage down chunk [128 d][128 k]
            const int row = tid >> 1, half = tid & 1;
            const uint4* src = g_Bd + nb * 4096 + row * 32 + kc * 16 + half * 8;
            uint4* dst = s4 + 2176 + row * 17 + half * 8;
            #pragma unroll
            for (int j = 0; j < 8; j++) dst[j] = src[j];
        }
        __syncthreads();

        const uint32_t xb = sbase;
        const uint32_t db = sbase + 34816;
        #pragma unroll
        for (int ks = 0; ks < 8; ks++) {
            uint32_t a[4][4], b[4][2];
            int acol = ks * 16 + 8 * (lane >> 4);
            #pragma unroll
            for (int mi = 0; mi < 4; mi++)
                ldmx4(a[mi], xb + (m_base + mi * 16 + (lane & 15)) * 272 + acol * 2);
            int bcol = ks * 16 + 8 * ((lane >> 3) & 1);
            #pragma unroll
            for (int ni = 0; ni < 4; ni++)
                ldmx2(b[ni], db + (n_base + ni * 8 + (lane & 7)) * 272 + bcol * 2);
            #pragma unroll
            for (int mi = 0; mi < 4; mi++)
                #pragma unroll
                for (int ni = 0; ni < 4; ni++)
                    mma_bf16(c[mi][ni], a[mi], b[ni]);
        }
    }
    __syncthreads();   // all reads of X/down done before overwrite

    // write Lo = bf16(C1) into region A; copy up^T full into region B
    #pragma unroll
    for (int mi = 0; mi < 4; mi++)
        #pragma unroll
        for (int ni = 0; ni < 4; ni++) {
            int r0 = m_base + mi * 16 + (lane >> 2);
            int cp = ((n_base + ni * 8) >> 1) + (lane & 3);
            s32[r0 * 68 + cp]       = pack_bf2(c[mi][ni][0], c[mi][ni][1]);
            s32[(r0 + 8) * 68 + cp] = pack_bf2(c[mi][ni][2], c[mi][ni][3]);
        }
    {
        const uint4* src = g_Bu + nb * 4096 + tid * 16;
        uint4* dst = s4 + 2176 + tid * 17;
        #pragma unroll
        for (int j = 0; j < 16; j++) dst[j] = src[j];
    }
    __syncthreads();

    // =================== GEMM2: out += rs*w_m * (Lo @ up^T) ===================
    const float rs = *rs_p;
    for (int half = 0; half < 2; half++) {
        #pragma unroll
        for (int mi = 0; mi < 4; mi++)
            #pragma unroll
            for (int ni = 0; ni < 4; ni++)
                #pragma unroll
                for (int q = 0; q < 4; q++) c[mi][ni][q] = 0.f;

        const uint32_t lb = sbase;
        const uint32_t ub = sbase + 34816;
        #pragma unroll
        for (int ks = 0; ks < 8; ks++) {
            uint32_t a[4][4], b[4][2];
            int acol = ks * 16 + 8 * (lane >> 4);
            #pragma unroll
            for (int mi = 0; mi < 4; mi++)
                ldmx4(a[mi], lb + (m_base + mi * 16 + (lane & 15)) * 272 + acol * 2);
            int bcol = ks * 16 + 8 * ((lane >> 3) & 1);
            #pragma unroll
            for (int ni = 0; ni < 4; ni++)
                ldmx2(b[ni], ub + (half * 128 + n_base + ni * 8 + (lane & 7)) * 272 + bcol * 2);
            #pragma unroll
            for (int mi = 0; mi < 4; mi++)
                #pragma unroll
                for (int ni = 0; ni < 4; ni++)
                    mma_bf16(c[mi][ni], a[mi], b[ni]);
        }
        // epilogue: RMW out
        #pragma unroll
        for (int mi = 0; mi < 4; mi++) {
            #pragma unroll
            for (int rsel = 0; rsel < 2; rsel++) {
                int m = m_base + mi * 16 + (lane >> 2) + rsel * 8;
                if (m < M) {
                    float sc = rs * wts_s[m];
                    float* o = out + (size_t)rows_s[m] * H + nb * BS
                             + half * 128 + n_base + (lane & 3) * 2;
                    #pragma unroll
                    for (int ni = 0; ni < 4; ni++) {
                        float2* p = (float2*)(o + ni * 8);
                        float2 t = *p;
                        t.x += sc * c[mi][ni][rsel * 2];
                        t.y += sc * c[mi][ni][rsel * 2 + 1];
                        *p = t;
                    }
                }
            }
        }
    }
}

// ---------------------------------------------------------------------------
extern "C" void kernel_launch(void* const* d_in, const int* in_sizes, int n_in,
                              void* d_out, int out_size)
{
    const float* x     = (const float*)d_in[0];
    const float* prior = (const float*)d_in[1];
    const float* sw    = (const float*)d_in[2];
    const float* sb    = (const float*)d_in[3];
    const float* dw    = (const float*)d_in[4];
    const float* uw    = (const float*)d_in[5];
    const float* rps   = (const float*)d_in[6];
    const float* rs    = (const float*)d_in[7];
    float* out = (float*)d_out;

    int rows = in_sizes[0] / H;   // 8192
    if (rows > MAXROWS) rows = MAXROWS;

    int smem_bytes = 34816 + 69632;   // 104448
    cudaFuncSetAttribute(adapter_kernel,
                         cudaFuncAttributeMaxDynamicSharedMemorySize, smem_bytes);

    zero_counts_kernel<<<1, 32>>>();
    convert_weights_kernel<<<dim3(NB, 2), 256>>>(dw, uw);
    route_kernel<<<(rows + RPC - 1) / RPC, 256>>>(x, prior, sw, sb, rps, out, rows);
    dim3 g2((rows + MT - 1) / MT, NB);
    adapter_kernel<<<g2, 256, smem_bytes>>>(x, rs, out);
}

// round 12
// speedup vs baseline: 1.6926x; 1.2569x over previous
#include <cuda_runtime.h>
#include <cuda_bf16.h>
#include <math.h>
#include <stdint.h>

#define H     4096
#define NB    16
#define BS    256
#define TOPK  4
#define RANK  128
#define MT    128
#define MAXROWS 8192
#define RPC   8        // rows per route CTA

// ---- device-global scratch (no allocations allowed) ----
__device__ int   g_counts[NB];
__device__ int   g_rows[NB * MAXROWS];
__device__ float g_wts [NB * MAXROWS];
// bf16 weights, pre-transposed to mma row.col B layout (k-contiguous):
// g_Bd[nb]: down^T  [128 d][256 k]   g_Bu[nb]: up^T [256 n][128 d]
__device__ uint4 g_Bd[NB * 4096];
__device__ uint4 g_Bu[NB * 4096];

__device__ __forceinline__ uint32_t smem_u32(const void* p) {
    uint32_t a;
    asm("{ .reg .u64 t; cvta.to.shared.u64 t, %1; cvt.u32.u64 %0, t; }"
        : "=r"(a) : "l"(p));
    return a;
}

__device__ __forceinline__ uint32_t pack_bf2(float a, float b) {
    uint16_t ua = __bfloat16_as_ushort(__float2bfloat16_rn(a));
    uint16_t ub = __bfloat16_as_ushort(__float2bfloat16_rn(b));
    return (uint32_t)ua | ((uint32_t)ub << 16);
}

__device__ __forceinline__ void ldmx4(uint32_t* r, uint32_t addr) {
    asm volatile("ldmatrix.sync.aligned.m8n8.x4.shared.b16 {%0,%1,%2,%3}, [%4];"
                 : "=r"(r[0]), "=r"(r[1]), "=r"(r[2]), "=r"(r[3]) : "r"(addr));
}
__device__ __forceinline__ void ldmx2(uint32_t* r, uint32_t addr) {
    asm volatile("ldmatrix.sync.aligned.m8n8.x2.shared.b16 {%0,%1}, [%2];"
                 : "=r"(r[0]), "=r"(r[1]) : "r"(addr));
}
__device__ __forceinline__ void mma_bf16(float* c, const uint32_t* a, const uint32_t* b) {
    asm volatile(
        "mma.sync.aligned.m16n8k16.row.col.f32.bf16.bf16.f32 "
        "{%0,%1,%2,%3}, {%4,%5,%6,%7}, {%8,%9}, {%0,%1,%2,%3};"
        : "+f"(c[0]), "+f"(c[1]), "+f"(c[2]), "+f"(c[3])
        : "r"(a[0]), "r"(a[1]), "r"(a[2]), "r"(a[3]), "r"(b[0]), "r"(b[1]));
}

__device__ __forceinline__ void cpa16(uint32_t dst, const void* src) {
    asm volatile("cp.async.cg.shared.global [%0], [%1], 16;"
                 :: "r"(dst), "l"(src) : "memory");
}
#define CPA_COMMIT() asm volatile("cp.async.commit_group;" ::: "memory")
#define CPA_WAIT(n)  asm volatile("cp.async.wait_group %0;" :: "n"(n) : "memory")

__device__ __forceinline__ float warp_sum(float v) {
    v += __shfl_down_sync(0xffffffffu, v, 16);
    v += __shfl_down_sync(0xffffffffu, v, 8);
    v += __shfl_down_sync(0xffffffffu, v, 4);
    v += __shfl_down_sync(0xffffffffu, v, 2);
    v += __shfl_down_sync(0xffffffffu, v, 1);
    return v;
}

// ---------------------------------------------------------------------------
// Weight pre-conversion: smem-tiled transpose (coalesced both sides) + bf16.
// Also zeroes g_counts (block (0,0)) — runs before route in-stream.
// ---------------------------------------------------------------------------
__global__ void __launch_bounds__(256) convert_weights_kernel(
    const float* __restrict__ down, const float* __restrict__ up)
{
    __shared__ float tile[32][33];
    const int nb = blockIdx.x;
    const int tx = threadIdx.x & 31, ty = threadIdx.x >> 5;   // 32 x 8

    if (blockIdx.y == 0) {
        if (nb == 0 && threadIdx.x < NB) g_counts[threadIdx.x] = 0;
        // src [256 k][128 d] fp32 -> dst [128 d][256 k] bf16
        const float* src = down + (size_t)nb * BS * RANK;
        __nv_bfloat16* dst = (__nv_bfloat16*)g_Bd + (size_t)nb * 32768;
        for (int t = 0; t < 32; t++) {                 // 8 k-tiles x 4 d-tiles
            int k0 = (t >> 2) * 32, d0 = (t & 3) * 32;
            __syncthreads();
            #pragma unroll
            for (int j = 0; j < 4; j++)
                tile[ty + j * 8][tx] = src[(k0 + ty + j * 8) * RANK + d0 + tx];
            __syncthreads();
            #pragma unroll
            for (int j = 0; j < 4; j++)
                dst[(d0 + ty + j * 8) * BS + k0 + tx] =
                    __float2bfloat16_rn(tile[tx][ty + j * 8]);
        }
    } else {
        // src [128 d][256 n] fp32 -> dst [256 n][128 d] bf16
        const float* src = up + (size_t)nb * RANK * BS;
        __nv_bfloat16* dst = (__nv_bfloat16*)g_Bu + (size_t)nb * 32768;
        for (int t = 0; t < 32; t++) {                 // 4 d-tiles x 8 n-tiles
            int d0 = (t >> 3) * 32, n0 = (t & 7) * 32;
            __syncthreads();
            #pragma unroll
            for (int j = 0; j < 4; j++)
                tile[ty + j * 8][tx] = src[(d0 + ty + j * 8) * BS + n0 + tx];
            __syncthreads();
            #pragma unroll
            for (int j = 0; j < 4; j++)
                dst[(n0 + ty + j * 8) * RANK + d0 + tx] =
                    __float2bfloat16_rn(tile[tx][ty + j * 8]);
        }
    }
}

// ---------------------------------------------------------------------------
// Kernel 1: routing + residual copy. 8 rows per CTA, one warp per row,
// spatial weights staged once in smem.
// ---------------------------------------------------------------------------
__global__ void __launch_bounds__(256) route_kernel(
    const float* __restrict__ x, const float* __restrict__ prior,
    const float* __restrict__ sw, const float* __restrict__ sb,
    const float* __restrict__ rps_p, float* __restrict__ out, int rows)
{
    __shared__ float4 swv[3 * 1024];   // 48 KB

    const int tid = threadIdx.x;
    for (int i = tid; i < 3 * 1024; i += 256) swv[i] = ((const float4*)sw)[i];
    __syncthreads();

    const int wid = tid >> 5, lane = tid & 31;
    const int row = blockIdx.x * RPC + wid;
    if (row >= rows) return;

    const float4* xv = (const float4*)(x + (size_t)row * H);
    float4*       ov = (float4*)(out + (size_t)row * H);

    float s = 0.f, s2 = 0.f, d0 = 0.f, d1 = 0.f, d2 = 0.f;
    float t0 = 0.f, t1 = 0.f, t2 = 0.f;

    #pragma unroll 4
    for (int i = lane; i < 1024; i += 32) {
        float4 v = xv[i];
        ov[i] = v;                       // fused residual copy
        float4 a = swv[i];
        float4 b = swv[i + 1024];
        float4 c = swv[i + 2048];
        s  += (v.x + v.y) + (v.z + v.w);
        s2 += v.x * v.x + v.y * v.y + v.z * v.z + v.w * v.w;
        d0 += v.x * a.x + v.y * a.y + v.z * a.z + v.w * a.w;
        d1 += v.x * b.x + v.y * b.y + v.z * b.z + v.w * b.w;
        d2 += v.x * c.x + v.y * c.y + v.z * c.z + v.w * c.w;
        t0 += (a.x + a.y) + (a.z + a.w);
        t1 += (b.x + b.y) + (b.z + b.w);
        t2 += (c.x + c.y) + (c.z + c.w);
    }

    float r[8] = {s, s2, d0, d1, d2, t0, t1, t2};
    #pragma unroll
    for (int j = 0; j < 8; j++) r[j] = warp_sum(r[j]);

    if (lane == 0) {
        const float invH = 1.0f / (float)H;
        float mu  = r[0] * invH;
        float var = fmaxf(r[1] * invH - mu * mu, 0.f);
        float rstd = rsqrtf(var + 1e-5f);
        float q0 = 3.0f / (1.0f + expf(-((r[2] - mu * r[5]) * rstd + sb[0])));
        float q1 = 3.0f / (1.0f + expf(-((r[3] - mu * r[6]) * rstd + sb[1])));
        float q2 = 3.0f / (1.0f + expf(-((r[4] - mu * r[7]) * rstd + sb[2])));

        const float rps = *rps_p;
        const float* pr = prior + (size_t)row * NB;
        float p[NB]; float psum = 0.f;
        #pragma unroll
        for (int i = 0; i < NB; i++) { p[i] = fmaxf(pr[i], 0.f); psum += p[i]; }
        float inv = 1.0f / fmaxf(psum, 1e-6f);

        float fused[NB];
        #pragma unroll
        for (int i = 0; i < NB; i++) {
            float cx = (float)(i & 3);
            float cy = (float)((i >> 2) & 3);
            float dx = q0 - cx, dy = q1 - cy, dz = q2;
            float sp = expf(-0.5f * (dx * dx + dy * dy + dz * dz));
            float bias = logf(p[i] * inv + 1e-6f);
            bias = fminf(fmaxf(bias, -6.0f), 0.0f);
            fused[i] = sp + rps * bias;
        }
        int   idx[TOPK]; float val[TOPK];
        #pragma unroll
        for (int k = 0; k < TOPK; k++) {
            int bi = 0; float bv = fused[0];
            #pragma unroll
            for (int i = 1; i < NB; i++)
                if (fused[i] > bv) { bv = fused[i]; bi = i; }
            idx[k] = bi; val[k] = bv; fused[bi] = -1e30f;
        }
        float mx = val[0];
        float e[TOPK], es = 0.f;
        #pragma unroll
        for (int k = 0; k < TOPK; k++) { e[k] = expf(val[k] - mx); es += e[k]; }
        float inve = 1.0f / es;
        #pragma unroll
        for (int k = 0; k < TOPK; k++) {
            int pos = atomicAdd(&g_counts[idx[k]], 1);
            if (pos < MAXROWS) {
                g_rows[idx[k] * MAXROWS + pos] = row;
                g_wts [idx[k] * MAXROWS + pos] = e[k] * inve;
            }
        }
    }
}

// ---------------------------------------------------------------------------
// Kernel 2: warp-MMA adapter (bf16 HMMA, fp32 accum), cp.async-pipelined.
// smem: region A (X/Lo) 34816B + region B ping-pong 2x34816B = 104448B.
// Weight stages prefetched one phase ahead via cp.async groups:
//   g0=down.kc0->B0, g1=down.kc1->B1, g2=up.h0->B0, g3=up.h1->B1.
// ---------------------------------------------------------------------------
__global__ void __launch_bounds__(256, 2) adapter_kernel(
    const float* __restrict__ x, const float* __restrict__ rs_p,
    float* __restrict__ out)
{
    const int nb = blockIdx.y;
    const int count = min(g_counts[nb], MAXROWS);
    const int m0 = blockIdx.x * MT;
    if (m0 >= count) return;
    const int M = min(MT, count - m0);

    extern __shared__ uint4 s4[];
    uint32_t* s32 = (uint32_t*)s4;
    const uint32_t sbase = smem_u32(s4);
    __shared__ int   rows_s[MT];
    __shared__ float wts_s[MT];

    const int tid  = threadIdx.x;
    const int lane = tid & 31, w = tid >> 5;
    const int m_base = (w >> 2) * 64, n_base = (w & 3) * 32;
    const int row = tid >> 1, half = tid & 1;        // staging roles

    const uint32_t A  = sbase;
    const uint32_t B0 = sbase + 34816;
    const uint32_t B1 = sbase + 69632;
    uint4* s4B0 = s4 + 2176;
    uint4* s4B1 = s4 + 4352;

    // g0: down kc=0 -> B0 (each thread 8x16B)
    {
        const uint4* src = g_Bd + nb * 4096 + row * 32 + half * 8;
        uint32_t dst = B0 + (row * 17 + half * 8) * 16;
        #pragma unroll
        for (int j = 0; j < 8; j++) cpa16(dst + j * 16, src + j);
        CPA_COMMIT();
    }

    if (tid < MT) {
        if (tid < M) {
            rows_s[tid] = g_rows[nb * MAXROWS + m0 + tid];
            wts_s[tid]  = g_wts [nb * MAXROWS + m0 + tid];
        } else {
            rows_s[tid] = g_rows[nb * MAXROWS + m0];
            wts_s[tid]  = 0.f;
        }
    }
    __syncthreads();   // rows_s visible

    float c[4][4][4];
    #pragma unroll
    for (int mi = 0; mi < 4; mi++)
        #pragma unroll
        for (int ni = 0; ni < 4; ni++)
            #pragma unroll
            for (int q = 0; q < 4; q++) c[mi][ni][q] = 0.f;

    // =================== GEMM1: C1[128m][128d] = X @ down^T ===================
    for (int kc = 0; kc < 2; kc++) {
        // stage X chunk, batched loads (MLP=8 before any STS)
        {
            const float4* src = (const float4*)(x + (size_t)rows_s[row] * H
                                                + nb * BS + kc * 128 + half * 64);
            uint4* dst = s4 + row * 17 + half * 8;
            float4 v[8];
            #pragma unroll
            for (int j = 0; j < 8; j++) v[j] = src[j];
            #pragma unroll
            for (int j = 0; j < 4; j++) {
                uint4 t;
                t.x = pack_bf2(v[2*j].x, v[2*j].y);   t.y = pack_bf2(v[2*j].z, v[2*j].w);
                t.z = pack_bf2(v[2*j+1].x, v[2*j+1].y); t.w = pack_bf2(v[2*j+1].z, v[2*j+1].w);
                dst[j] = t;
            }
            #pragma unroll
            for (int j = 0; j < 8; j++) v[j] = src[8 + j];
            #pragma unroll
            for (int j = 0; j < 4; j++) {
                uint4 t;
                t.x = pack_bf2(v[2*j].x, v[2*j].y);   t.y = pack_bf2(v[2*j].z, v[2*j].w);
                t.z = pack_bf2(v[2*j+1].x, v[2*j+1].y); t.w = pack_bf2(v[2*j+1].z, v[2*j+1].w);
                dst[4 + j] = t;
            }
        }
        // prefetch next weight stage
        if (kc == 0) {
            const uint4* src = g_Bd + nb * 4096 + row * 32 + 16 + half * 8;  // down kc1
            uint32_t dst = B1 + (row * 17 + half * 8) * 16;
            #pragma unroll
            for (int j = 0; j < 8; j++) cpa16(dst + j * 16, src + j);
            CPA_COMMIT();                              // g1
        } else {
            const uint4* src = g_Bu + nb * 4096 + row * 16 + half * 8;       // up h0
            uint32_t dst = B0 + (row * 17 + half * 8) * 16;
            #pragma unroll
            for (int j = 0; j < 8; j++) cpa16(dst + j * 16, src + j);
            CPA_COMMIT();                              // g2
        }
        CPA_WAIT(1);        // oldest group (this kc's down stage) complete
        __syncthreads();

        const uint32_t db = (kc == 0) ? B0 : B1;
        #pragma unroll
        for (int ks = 0; ks < 8; ks++) {
            uint32_t a[4][4], b[4][2];
            int acol = ks * 16 + 8 * (lane >> 4);
            #pragma unroll
            for (int mi = 0; mi < 4; mi++)
                ldmx4(a[mi], A + (m_base + mi * 16 + (lane & 15)) * 272 + acol * 2);
            int bcol = ks * 16 + 8 * ((lane >> 3) & 1);
            #pragma unroll
            for (int ni = 0; ni < 4; ni++)
                ldmx2(b[ni], db + (n_base + ni * 8 + (lane & 7)) * 272 + bcol * 2);
            #pragma unroll
            for (int mi = 0; mi < 4; mi++)
                #pragma unroll
                for (int ni = 0; ni < 4; ni++)
                    mma_bf16(c[mi][ni], a[mi], b[ni]);
        }
        __syncthreads();    // A (and the just-read B half) free for reuse
    }

    // write Lo = bf16(C1) into region A; prefetch up h1 -> B1 (g3)
    #pragma unroll
    for (int mi = 0; mi < 4; mi++)
        #pragma unroll
        for (int ni = 0; ni < 4; ni++) {
            int r0 = m_base + mi * 16 + (lane >> 2);
            int cp = ((n_base + ni * 8) >> 1) + (lane & 3);
            s32[r0 * 68 + cp]       = pack_bf2(c[mi][ni][0], c[mi][ni][1]);
            s32[(r0 + 8) * 68 + cp] = pack_bf2(c[mi][ni][2], c[mi][ni][3]);
        }
    {
        const uint4* src = g_Bu + nb * 4096 + (128 + row) * 16 + half * 8;   // up h1
        uint32_t dst = B1 + (row * 17 + half * 8) * 16;
        #pragma unroll
        for (int j = 0; j < 8; j++) cpa16(dst + j * 16, src + j);
        CPA_COMMIT();                                  // g3
    }
    CPA_WAIT(1);            // g2 (up h0) complete
    __syncthreads();

    // =================== GEMM2: out += rs*w_m * (Lo @ up^T) ===================
    const float rs = *rs_p;
    for (int hf = 0; hf < 2; hf++) {
        #pragma unroll
        for (int mi = 0; mi < 4; mi++)
            #pragma unroll
            for (int ni = 0; ni < 4; ni++)
                #pragma unroll
                for (int q = 0; q < 4; q++) c[mi][ni][q] = 0.f;

        const uint32_t ub = (hf == 0) ? B0 : B1;
        #pragma unroll
        for (int ks = 0; ks < 8; ks++) {
            uint32_t a[4][4], b[4][2];
            int acol = ks * 16 + 8 * (lane >> 4);
            #pragma unroll
            for (int mi = 0; mi < 4; mi++)
                ldmx4(a[mi], A + (m_base + mi * 16 + (lane & 15)) * 272 + acol * 2);
            int bcol = ks * 16 + 8 * ((lane >> 3) & 1);
            #pragma unroll
            for (int ni = 0; ni < 4; ni++)
                ldmx2(b[ni], ub + (n_base + ni * 8 + (lane & 7)) * 272 + bcol * 2);
            #pragma unroll
            for (int mi = 0; mi < 4; mi++)
                #pragma unroll
                for (int ni = 0; ni < 4; ni++)
                    mma_bf16(c[mi][ni], a[mi], b[ni]);
        }
        // epilogue: RMW out
        #pragma unroll
        for (int mi = 0; mi < 4; mi++) {
            #pragma unroll
            for (int rsel = 0; rsel < 2; rsel++) {
                int m = m_base + mi * 16 + (lane >> 2) + rsel * 8;
                if (m < M) {
                    float sc = rs * wts_s[m];
                    float* o = out + (size_t)rows_s[m] * H + nb * BS
                             + hf * 128 + n_base + (lane & 3) * 2;
                    #pragma unroll
                    for (int ni = 0; ni < 4; ni++) {
                        float2* p = (float2*)(o + ni * 8);
                        float2 t = *p;
                        t.x += sc * c[mi][ni][rsel * 2];
                        t.y += sc * c[mi][ni][rsel * 2 + 1];
                        *p = t;
                    }
                }
            }
        }
        if (hf == 0) {
            CPA_WAIT(0);    // g3 (up h1) complete
            __syncthreads();
        }
    }
    (void)s4B0; (void)s4B1;
}

// ---------------------------------------------------------------------------
extern "C" void kernel_launch(void* const* d_in, const int* in_sizes, int n_in,
                              void* d_out, int out_size)
{
    const float* x     = (const float*)d_in[0];
    const float* prior = (const float*)d_in[1];
    const float* sw    = (const float*)d_in[2];
    const float* sb    = (const float*)d_in[3];
    const float* dw    = (const float*)d_in[4];
    const float* uw    = (const float*)d_in[5];
    const float* rps   = (const float*)d_in[6];
    const float* rs    = (const float*)d_in[7];
    float* out = (float*)d_out;

    int rows = in_sizes[0] / H;   // 8192
    if (rows > MAXROWS) rows = MAXROWS;

    int smem_bytes = 34816 * 3;   // 104448
    cudaFuncSetAttribute(adapter_kernel,
                         cudaFuncAttributeMaxDynamicSharedMemorySize, smem_bytes);

    convert_weights_kernel<<<dim3(NB, 2), 256>>>(dw, uw);   // also zeroes g_counts
    route_kernel<<<(rows + RPC - 1) / RPC, 256>>>(x, prior, sw, sb, rps, out, rows);
    dim3 g2((rows + MT - 1) / MT, NB);
    adapter_kernel<<<g2, 256, smem_bytes>>>(x, rs, out);
}

// round 15
// speedup vs baseline: 1.8589x; 1.0983x over previous
#include <cuda_runtime.h>
#include <cuda_bf16.h>
#include <math.h>
#include <stdint.h>

#define H     4096
#define NB    16
#define BS    256
#define TOPK  4
#define RANK  128
#define MT    128
#define MAXROWS 8192
#define RPC   8        // rows per route CTA

// ---- device-global scratch (no allocations allowed) ----
__device__ int   g_counts[NB];
__device__ int   g_rows[NB * MAXROWS];
__device__ float g_wts [NB * MAXROWS];
// bf16 weights, pre-transposed to mma row.col B layout (k-contiguous):
// g_Bd[nb]: down^T  [128 d][256 k]   g_Bu[nb]: up^T [256 n][128 d]
__device__ uint4 g_Bd[NB * 4096];
__device__ uint4 g_Bu[NB * 4096];

__device__ __forceinline__ uint32_t smem_u32(const void* p) {
    uint32_t a;
    asm("{ .reg .u64 t; cvta.to.shared.u64 t, %1; cvt.u32.u64 %0, t; }"
        : "=r"(a) : "l"(p));
    return a;
}

__device__ __forceinline__ uint32_t pack_bf2(float a, float b) {
    uint16_t ua = __bfloat16_as_ushort(__float2bfloat16_rn(a));
    uint16_t ub = __bfloat16_as_ushort(__float2bfloat16_rn(b));
    return (uint32_t)ua | ((uint32_t)ub << 16);
}

__device__ __forceinline__ void ldmx4(uint32_t* r, uint32_t addr) {
    asm volatile("ldmatrix.sync.aligned.m8n8.x4.shared.b16 {%0,%1,%2,%3}, [%4];"
                 : "=r"(r[0]), "=r"(r[1]), "=r"(r[2]), "=r"(r[3]) : "r"(addr));
}
__device__ __forceinline__ void ldmx2(uint32_t* r, uint32_t addr) {
    asm volatile("ldmatrix.sync.aligned.m8n8.x2.shared.b16 {%0,%1}, [%2];"
                 : "=r"(r[0]), "=r"(r[1]) : "r"(addr));
}
__device__ __forceinline__ void mma_bf16(float* c, const uint32_t* a, const uint32_t* b) {
    asm volatile(
        "mma.sync.aligned.m16n8k16.row.col.f32.bf16.bf16.f32 "
        "{%0,%1,%2,%3}, {%4,%5,%6,%7}, {%8,%9}, {%0,%1,%2,%3};"
        : "+f"(c[0]), "+f"(c[1]), "+f"(c[2]), "+f"(c[3])
        : "r"(a[0]), "r"(a[1]), "r"(a[2]), "r"(a[3]), "r"(b[0]), "r"(b[1]));
}

__device__ __forceinline__ void cpa16(uint32_t dst, const void* src) {
    asm volatile("cp.async.cg.shared.global [%0], [%1], 16;"
                 :: "r"(dst), "l"(src) : "memory");
}
#define CPA_COMMIT() asm volatile("cp.async.commit_group;" ::: "memory")
#define CPA_WAIT(n)  asm volatile("cp.async.wait_group %0;" :: "n"(n) : "memory")

__device__ __forceinline__ float warp_sum(float v) {
    v += __shfl_down_sync(0xffffffffu, v, 16);
    v += __shfl_down_sync(0xffffffffu, v, 8);
    v += __shfl_down_sync(0xffffffffu, v, 4);
    v += __shfl_down_sync(0xffffffffu, v, 2);
    v += __shfl_down_sync(0xffffffffu, v, 1);
    return v;
}

// ---------------------------------------------------------------------------
// Weight pre-conversion: smem-tiled transpose (coalesced both sides) + bf16.
// Parallelized: grid (NB*8, 2), each CTA does 4 of the 32 tiles per matrix.
// Block (0,0) also zeroes g_counts (kernel completes before route launches).
// ---------------------------------------------------------------------------
__global__ void __launch_bounds__(256) convert_weights_kernel(
    const float* __restrict__ down, const float* __restrict__ up)
{
    __shared__ float tile[32][33];
    const int nb   = blockIdx.x >> 3;
    const int part = blockIdx.x & 7;
    const int tx = threadIdx.x & 31, ty = threadIdx.x >> 5;   // 32 x 8

    if (blockIdx.y == 0) {
        if (blockIdx.x == 0 && threadIdx.x < NB) g_counts[threadIdx.x] = 0;
        // src [256 k][128 d] fp32 -> dst [128 d][256 k] bf16
        const float* src = down + (size_t)nb * BS * RANK;
        __nv_bfloat16* dst = (__nv_bfloat16*)g_Bd + (size_t)nb * 32768;
        for (int tt = 0; tt < 4; tt++) {               // 8 k-tiles x 4 d-tiles
            int t = part * 4 + tt;
            int k0 = (t >> 2) * 32, d0 = (t & 3) * 32;
            __syncthreads();
            #pragma unroll
            for (int j = 0; j < 4; j++)
                tile[ty + j * 8][tx] = src[(k0 + ty + j * 8) * RANK + d0 + tx];
            __syncthreads();
            #pragma unroll
            for (int j = 0; j < 4; j++)
                dst[(d0 + ty + j * 8) * BS + k0 + tx] =
                    __float2bfloat16_rn(tile[tx][ty + j * 8]);
        }
    } else {
        // src [128 d][256 n] fp32 -> dst [256 n][128 d] bf16
        const float* src = up + (size_t)nb * RANK * BS;
        __nv_bfloat16* dst = (__nv_bfloat16*)g_Bu + (size_t)nb * 32768;
        for (int tt = 0; tt < 4; tt++) {               // 4 d-tiles x 8 n-tiles
            int t = part * 4 + tt;
            int d0 = (t >> 3) * 32, n0 = (t & 7) * 32;
            __syncthreads();
            #pragma unroll
            for (int j = 0; j < 4; j++)
                tile[ty + j * 8][tx] = src[(d0 + ty + j * 8) * BS + n0 + tx];
            __syncthreads();
            #pragma unroll
            for (int j = 0; j < 4; j++)
                dst[(n0 + ty + j * 8) * RANK + d0 + tx] =
                    __float2bfloat16_rn(tile[tx][ty + j * 8]);
        }
    }
}

// ---------------------------------------------------------------------------
// Kernel 1: routing + residual copy. 8 rows per CTA, one warp per row,
// spatial weights staged once in smem.
// ---------------------------------------------------------------------------
__global__ void __launch_bounds__(256) route_kernel(
    const float* __restrict__ x, const float* __restrict__ prior,
    const float* __restrict__ sw, const float* __restrict__ sb,
    const float* __restrict__ rps_p, float* __restrict__ out, int rows)
{
    __shared__ float4 swv[3 * 1024];   // 48 KB

    const int tid = threadIdx.x;
    for (int i = tid; i < 3 * 1024; i += 256) swv[i] = ((const float4*)sw)[i];
    __syncthreads();

    const int wid = tid >> 5, lane = tid & 31;
    const int row = blockIdx.x * RPC + wid;
    if (row >= rows) return;

    const float4* xv = (const float4*)(x + (size_t)row * H);
    float4*       ov = (float4*)(out + (size_t)row * H);

    float s = 0.f, s2 = 0.f, d0 = 0.f, d1 = 0.f, d2 = 0.f;
    float t0 = 0.f, t1 = 0.f, t2 = 0.f;

    #pragma unroll 4
    for (int i = lane; i < 1024; i += 32) {
        float4 v = xv[i];
        ov[i] = v;                       // fused residual copy
        float4 a = swv[i];
        float4 b = swv[i + 1024];
        float4 c = swv[i + 2048];
        s  += (v.x + v.y) + (v.z + v.w);
        s2 += v.x * v.x + v.y * v.y + v.z * v.z + v.w * v.w;
        d0 += v.x * a.x + v.y * a.y + v.z * a.z + v.w * a.w;
        d1 += v.x * b.x + v.y * b.y + v.z * b.z + v.w * b.w;
        d2 += v.x * c.x + v.y * c.y + v.z * c.z + v.w * c.w;
        t0 += (a.x + a.y) + (a.z + a.w);
        t1 += (b.x + b.y) + (b.z + b.w);
        t2 += (c.x + c.y) + (c.z + c.w);
    }

    float r[8] = {s, s2, d0, d1, d2, t0, t1, t2};
    #pragma unroll
    for (int j = 0; j < 8; j++) r[j] = warp_sum(r[j]);

    if (lane == 0) {
        const float invH = 1.0f / (float)H;
        float mu  = r[0] * invH;
        float var = fmaxf(r[1] * invH - mu * mu, 0.f);
        float rstd = rsqrtf(var + 1e-5f);
        float q0 = 3.0f / (1.0f + expf(-((r[2] - mu * r[5]) * rstd + sb[0])));
        float q1 = 3.0f / (1.0f + expf(-((r[3] - mu * r[6]) * rstd + sb[1])));
        float q2 = 3.0f / (1.0f + expf(-((r[4] - mu * r[7]) * rstd + sb[2])));

        const float rps = *rps_p;
        const float* pr = prior + (size_t)row * NB;
        float p[NB]; float psum = 0.f;
        #pragma unroll
        for (int i = 0; i < NB; i++) { p[i] = fmaxf(pr[i], 0.f); psum += p[i]; }
        float inv = 1.0f / fmaxf(psum, 1e-6f);

        float fused[NB];
        #pragma unroll
        for (int i = 0; i < NB; i++) {
            float cx = (float)(i & 3);
            float cy = (float)((i >> 2) & 3);
            float dx = q0 - cx, dy = q1 - cy, dz = q2;
            float sp = expf(-0.5f * (dx * dx + dy * dy + dz * dz));
            float bias = logf(p[i] * inv + 1e-6f);
            bias = fminf(fmaxf(bias, -6.0f), 0.0f);
            fused[i] = sp + rps * bias;
        }
        int   idx[TOPK]; float val[TOPK];
        #pragma unroll
        for (int k = 0; k < TOPK; k++) {
            int bi = 0; float bv = fused[0];
            #pragma unroll
            for (int i = 1; i < NB; i++)
                if (fused[i] > bv) { bv = fused[i]; bi = i; }
            idx[k] = bi; val[k] = bv; fused[bi] = -1e30f;
        }
        float mx = val[0];
        float e[TOPK], es = 0.f;
        #pragma unroll
        for (int k = 0; k < TOPK; k++) { e[k] = expf(val[k] - mx); es += e[k]; }
        float inve = 1.0f / es;
        #pragma unroll
        for (int k = 0; k < TOPK; k++) {
            int pos = atomicAdd(&g_counts[idx[k]], 1);
            if (pos < MAXROWS) {
                g_rows[idx[k] * MAXROWS + pos] = row;
                g_wts [idx[k] * MAXROWS + pos] = e[k] * inve;
            }
        }
    }
}

// ---------------------------------------------------------------------------
// Kernel 2: warp-MMA adapter (bf16 HMMA, fp32 accum), cp.async-pipelined.
// smem: region A (X/Lo) 34816B + region B ping-pong 2x34816B = 104448B.
// Weight stages prefetched one phase ahead via cp.async groups:
//   g0=down.kc0->B0, g1=down.kc1->B1, g2=up.h0->B0, g3=up.h1->B1.
// ---------------------------------------------------------------------------
__global__ void __launch_bounds__(256, 2) adapter_kernel(
    const float* __restrict__ x, const float* __restrict__ rs_p,
    float* __restrict__ out)
{
    const int nb = blockIdx.y;
    const int count = min(g_counts[nb], MAXROWS);
    const int m0 = blockIdx.x * MT;
    if (m0 >= count) return;
    const int M = min(MT, count - m0);

    extern __shared__ uint4 s4[];
    uint32_t* s32 = (uint32_t*)s4;
    const uint32_t sbase = smem_u32(s4);
    __shared__ int   rows_s[MT];
    __shared__ float wts_s[MT];

    const int tid  = threadIdx.x;
    const int lane = tid & 31, w = tid >> 5;
    const int m_base = (w >> 2) * 64, n_base = (w & 3) * 32;
    const int row = tid >> 1, half = tid & 1;        // staging roles

    const uint32_t A  = sbase;
    const uint32_t B0 = sbase + 34816;
    const uint32_t B1 = sbase + 69632;

    // g0: down kc=0 -> B0 (each thread 8x16B)
    {
        const uint4* src = g_Bd + nb * 4096 + row * 32 + half * 8;
        uint32_t dst = B0 + (row * 17 + half * 8) * 16;
        #pragma unroll
        for (int j = 0; j < 8; j++) cpa16(dst + j * 16, src + j);
        CPA_COMMIT();
    }

    if (tid < MT) {
        if (tid < M) {
            rows_s[tid] = g_rows[nb * MAXROWS + m0 + tid];
            wts_s[tid]  = g_wts [nb * MAXROWS + m0 + tid];
        } else {
            rows_s[tid] = g_rows[nb * MAXROWS + m0];
            wts_s[tid]  = 0.f;
        }
    }
    __syncthreads();   // rows_s visible

    float c[4][4][4];
    #pragma unroll
    for (int mi = 0; mi < 4; mi++)
        #pragma unroll
        for (int ni = 0; ni < 4; ni++)
            #pragma unroll
            for (int q = 0; q < 4; q++) c[mi][ni][q] = 0.f;

    // =================== GEMM1: C1[128m][128d] = X @ down^T ===================
    for (int kc = 0; kc < 2; kc++) {
        // stage X chunk, batched loads (MLP=8 before any STS)
        {
            const float4* src = (const float4*)(x + (size_t)rows_s[row] * H
                                                + nb * BS + kc * 128 + half * 64);
            uint4* dst = s4 + row * 17 + half * 8;
            float4 v[8];
            #pragma unroll
            for (int j = 0; j < 8; j++) v[j] = src[j];
            #pragma unroll
            for (int j = 0; j < 4; j++) {
                uint4 t;
                t.x = pack_bf2(v[2*j].x, v[2*j].y);   t.y = pack_bf2(v[2*j].z, v[2*j].w);
                t.z = pack_bf2(v[2*j+1].x, v[2*j+1].y); t.w = pack_bf2(v[2*j+1].z, v[2*j+1].w);
                dst[j] = t;
            }
            #pragma unroll
            for (int j = 0; j < 8; j++) v[j] = src[8 + j];
            #pragma unroll
            for (int j = 0; j < 4; j++) {
                uint4 t;
                t.x = pack_bf2(v[2*j].x, v[2*j].y);   t.y = pack_bf2(v[2*j].z, v[2*j].w);
                t.z = pack_bf2(v[2*j+1].x, v[2*j+1].y); t.w = pack_bf2(v[2*j+1].z, v[2*j+1].w);
                dst[4 + j] = t;
            }
        }
        // prefetch next weight stage
        if (kc == 0) {
            const uint4* src = g_Bd + nb * 4096 + row * 32 + 16 + half * 8;  // down kc1
            uint32_t dst = B1 + (row * 17 + half * 8) * 16;
            #pragma unroll
            for (int j = 0; j < 8; j++) cpa16(dst + j * 16, src + j);
            CPA_COMMIT();                              // g1
        } else {
            const uint4* src = g_Bu + nb * 4096 + row * 16 + half * 8;       // up h0
            uint32_t dst = B0 + (row * 17 + half * 8) * 16;
            #pragma unroll
            for (int j = 0; j < 8; j++) cpa16(dst + j * 16, src + j);
            CPA_COMMIT();                              // g2
        }
        CPA_WAIT(1);        // oldest group (this kc's down stage) complete
        __syncthreads();

        const uint32_t db = (kc == 0) ? B0 : B1;
        #pragma unroll
        for (int ks = 0; ks < 8; ks++) {
            uint32_t a[4][4], b[4][2];
            int acol = ks * 16 + 8 * (lane >> 4);
            #pragma unroll
            for (int mi = 0; mi < 4; mi++)
                ldmx4(a[mi], A + (m_base + mi * 16 + (lane & 15)) * 272 + acol * 2);
            int bcol = ks * 16 + 8 * ((lane >> 3) & 1);
            #pragma unroll
            for (int ni = 0; ni < 4; ni++)
                ldmx2(b[ni], db + (n_base + ni * 8 + (lane & 7)) * 272 + bcol * 2);
            #pragma unroll
            for (int mi = 0; mi < 4; mi++)
                #pragma unroll
                for (int ni = 0; ni < 4; ni++)
                    mma_bf16(c[mi][ni], a[mi], b[ni]);
        }
        __syncthreads();    // A (and the just-read B half) free for reuse
    }

    // write Lo = bf16(C1) into region A; prefetch up h1 -> B1 (g3)
    #pragma unroll
    for (int mi = 0; mi < 4; mi++)
        #pragma unroll
        for (int ni = 0; ni < 4; ni++) {
            int r0 = m_base + mi * 16 + (lane >> 2);
            int cp = ((n_base + ni * 8) >> 1) + (lane & 3);
            s32[r0 * 68 + cp]       = pack_bf2(c[mi][ni][0], c[mi][ni][1]);
            s32[(r0 + 8) * 68 + cp] = pack_bf2(c[mi][ni][2], c[mi][ni][3]);
        }
    {
        const uint4* src = g_Bu + nb * 4096 + (128 + row) * 16 + half * 8;   // up h1
        uint32_t dst = B1 + (row * 17 + half * 8) * 16;
        #pragma unroll
        for (int j = 0; j < 8; j++) cpa16(dst + j * 16, src + j);
        CPA_COMMIT();                                  // g3
    }
    CPA_WAIT(1);            // g2 (up h0) complete
    __syncthreads();

    // =================== GEMM2: out += rs*w_m * (Lo @ up^T) ===================
    const float rs = *rs_p;
    for (int hf = 0; hf < 2; hf++) {
        #pragma unroll
        for (int mi = 0; mi < 4; mi++)
            #pragma unroll
            for (int ni = 0; ni < 4; ni++)
                #pragma unroll
                for (int q = 0; q < 4; q++) c[mi][ni][q] = 0.f;

        const uint32_t ub = (hf == 0) ? B0 : B1;
        #pragma unroll
        for (int ks = 0; ks < 8; ks++) {
            uint32_t a[4][4], b[4][2];
            int acol = ks * 16 + 8 * (lane >> 4);
            #pragma unroll
            for (int mi = 0; mi < 4; mi++)
                ldmx4(a[mi], A + (m_base + mi * 16 + (lane & 15)) * 272 + acol * 2);
            int bcol = ks * 16 + 8 * ((lane >> 3) & 1);
            #pragma unroll
            for (int ni = 0; ni < 4; ni++)
                ldmx2(b[ni], ub + (n_base + ni * 8 + (lane & 7)) * 272 + bcol * 2);
            #pragma unroll
            for (int mi = 0; mi < 4; mi++)
                #pragma unroll
                for (int ni = 0; ni < 4; ni++)
                    mma_bf16(c[mi][ni], a[mi], b[ni]);
        }
        // epilogue: RMW out
        #pragma unroll
        for (int mi = 0; mi < 4; mi++) {
            #pragma unroll
            for (int rsel = 0; rsel < 2; rsel++) {
                int m = m_base + mi * 16 + (lane >> 2) + rsel * 8;
                if (m < M) {
                    float sc = rs * wts_s[m];
                    float* o = out + (size_t)rows_s[m] * H + nb * BS
                             + hf * 128 + n_base + (lane & 3) * 2;
                    #pragma unroll
                    for (int ni = 0; ni < 4; ni++) {
                        float2* p = (float2*)(o + ni * 8);
                        float2 t = *p;
                        t.x += sc * c[mi][ni][rsel * 2];
                        t.y += sc * c[mi][ni][rsel * 2 + 1];
                        *p = t;
                    }
                }
            }
        }
        if (hf == 0) {
            CPA_WAIT(0);    // g3 (up h1) complete
            __syncthreads();
        }
    }
}

// ---------------------------------------------------------------------------
extern "C" void kernel_launch(void* const* d_in, const int* in_sizes, int n_in,
                              void* d_out, int out_size)
{
    const float* x     = (const float*)d_in[0];
    const float* prior = (const float*)d_in[1];
    const float* sw    = (const float*)d_in[2];
    const float* sb    = (const float*)d_in[3];
    const float* dw    = (const float*)d_in[4];
    const float* uw    = (const float*)d_in[5];
    const float* rps   = (const float*)d_in[6];
    const float* rs    = (const float*)d_in[7];
    float* out = (float*)d_out;

    int rows = in_sizes[0] / H;   // 8192
    if (rows > MAXROWS) rows = MAXROWS;

    int smem_bytes = 34816 * 3;   // 104448
    cudaFuncSetAttribute(adapter_kernel,
                         cudaFuncAttributeMaxDynamicSharedMemorySize, smem_bytes);

    convert_weights_kernel<<<dim3(NB * 8, 2), 256>>>(dw, uw);   // also zeroes g_counts
    route_kernel<<<(rows + RPC - 1) / RPC, 256>>>(x, prior, sw, sb, rps, out, rows);
    dim3 g2((rows + MT - 1) / MT, NB);
    adapter_kernel<<<g2, 256, smem_bytes>>>(x, rs, out);
}